// round 5
// baseline (speedup 1.0000x reference)
#include <cuda_runtime.h>
#include <cuda_fp16.h>
#include <cuda_bf16.h>
#include <math.h>

#define NN 100000
#define EE 1600000
#define NEG_SLOPE 0.2f
#define SCAN_B 512
#define NBLK ((NN + SCAN_B - 1) / SCAN_B)   // 196

// ---------------- scratch (device globals) ----------------
__device__ __half2 g_h1h[NN * 32];   // layer1 GEMM output, fp16 packed [N, 32 pairs]
__device__ __half  g_as1h[NN * 8];   // per-node/head src logit (fp16)
__device__ float   g_ad1[NN * 8];    // per-node/head dst logit (fp32, read once per warp)
__device__ float   g_out1[NN * 64];  // layer1 final (ELU'd), fp32 (feeds GEMM2)
__device__ __half  g_g2h[NN * 16];   // layer2 GEMM output (fp16)
__device__ float   g_as2[NN];
__device__ float   g_ad2[NN];
__device__ int     g_deg[NN];
__device__ int     g_off[NN];
__device__ int     g_pos[NN];
__device__ int     g_csr[EE];        // src node ids, grouped by dst
__device__ int     g_bsum[NBLK];

// packed f32x2 FMA (FFMA2) — only reachable via PTX
__device__ __forceinline__ void ffma2(unsigned long long& acc,
                                      unsigned long long a,
                                      unsigned long long b) {
    asm("fma.rn.f32x2 %0, %1, %2, %3;" : "=l"(acc) : "l"(a), "l"(b), "l"(acc));
}
__device__ __forceinline__ unsigned long long pack2(float lo, float hi) {
    unsigned long long r;
    asm("mov.b64 %0, {%1, %2};" : "=l"(r) : "f"(lo), "f"(hi));
    return r;
}

union F4U {
    float4 f;
    unsigned long long u[2];
};
union U2F {
    unsigned long long u;
    float f[2];
};

// ---------------- K0: zero degree histogram ----------------
__global__ void k0_init() {
    int i = blockIdx.x * blockDim.x + threadIdx.x;
    if (i < NN) g_deg[i] = 0;
}

// ---------------- CSR build ----------------
__global__ void k_hist(const int* __restrict__ dst) {
    int e = blockIdx.x * blockDim.x + threadIdx.x;
    if (e < EE) atomicAdd(&g_deg[dst[e]], 1);
}

__global__ void s1_scan() {
    __shared__ int sd[SCAN_B];
    int i = blockIdx.x * SCAN_B + threadIdx.x;
    int v = (i < NN) ? g_deg[i] : 0;
    sd[threadIdx.x] = v;
    __syncthreads();
    for (int ofs = 1; ofs < SCAN_B; ofs <<= 1) {
        int t = (threadIdx.x >= ofs) ? sd[threadIdx.x - ofs] : 0;
        __syncthreads();
        sd[threadIdx.x] += t;
        __syncthreads();
    }
    if (i < NN) g_off[i] = sd[threadIdx.x] - v;           // exclusive within block
    if (threadIdx.x == SCAN_B - 1) g_bsum[blockIdx.x] = sd[threadIdx.x];
}

__global__ void s3_apply() {
    __shared__ int sbase;
    int b = blockIdx.x;
    if (threadIdx.x < 32) {
        int p = 0;
        for (int i = threadIdx.x; i < b; i += 32) p += g_bsum[i];
#pragma unroll
        for (int o = 16; o; o >>= 1) p += __shfl_xor_sync(0xFFFFFFFFu, p, o);
        if (threadIdx.x == 0) sbase = p;
    }
    __syncthreads();
    int i = b * SCAN_B + threadIdx.x;
    if (i < NN) {
        int o = g_off[i] + sbase;
        g_off[i] = o;
        g_pos[i] = o;
    }
}

__global__ void k_scatter(const int* __restrict__ src, const int* __restrict__ dst) {
    int e = blockIdx.x * blockDim.x + threadIdx.x;
    if (e >= EE) return;
    int d = dst[e];
    int p = atomicAdd(&g_pos[d], 1);
    g_csr[p] = src[e];
}

// ---------------- K1: h1 = x @ W1 (+ attention logits), FFMA2 inner loop ----------------
__global__ void __launch_bounds__(256) k1_gemm1(
    const float* __restrict__ x, const float* __restrict__ W1,
    const float* __restrict__ a1s, const float* __restrict__ a1d)
{
    __shared__ float sW[128 * 64];
    __shared__ float sA[128];
    for (int i = threadIdx.x; i < 128 * 64; i += blockDim.x) sW[i] = W1[i];
    for (int i = threadIdx.x; i < 128; i += blockDim.x)
        sA[i] = (i < 64) ? a1s[i] : a1d[i - 64];
    __syncthreads();

    int row = blockIdx.x * blockDim.x + threadIdx.x;
    if (row >= NN) return;

    unsigned long long acc2[32];
#pragma unroll
    for (int j = 0; j < 32; j++) acc2[j] = 0ULL;

    const float4* x4 = (const float4*)(x + (size_t)row * 128);
#pragma unroll 1
    for (int kc = 0; kc < 32; kc++) {
        float4 xv = __ldg(x4 + kc);
#pragma unroll
        for (int t = 0; t < 4; t++) {
            float xs = (t == 0) ? xv.x : (t == 1) ? xv.y : (t == 2) ? xv.z : xv.w;
            unsigned long long xs2 = pack2(xs, xs);
            const float4* wrow = (const float4*)(sW + (kc * 4 + t) * 64);
#pragma unroll
            for (int j4 = 0; j4 < 16; j4++) {
                F4U w;
                w.f = wrow[j4];
                ffma2(acc2[j4 * 2 + 0], xs2, w.u[0]);
                ffma2(acc2[j4 * 2 + 1], xs2, w.u[1]);
            }
        }
    }

    // unpack, store fp16 h1, compute logits
    float acc[64];
#pragma unroll
    for (int j = 0; j < 32; j++) {
        U2F u;
        u.u = acc2[j];
        acc[j * 2] = u.f[0];
        acc[j * 2 + 1] = u.f[1];
    }

    __half2* h1o = g_h1h + (size_t)row * 32;
#pragma unroll
    for (int j = 0; j < 32; j++)
        h1o[j] = __floats2half2_rn(acc[j * 2], acc[j * 2 + 1]);

#pragma unroll
    for (int h = 0; h < 8; h++) {
        float s = 0.0f, d = 0.0f;
#pragma unroll
        for (int q = 0; q < 8; q++) {
            s += acc[h * 8 + q] * sA[h * 8 + q];
            d += acc[h * 8 + q] * sA[64 + h * 8 + q];
        }
        g_as1h[row * 8 + h] = __float2half(s);
        g_ad1[row * 8 + h] = d;
    }
}

// ---------------- G1: warp-per-dst gather, 4-edge batched logits, fp16 feeds ----------------
__global__ void __launch_bounds__(256) g1_gather(const float* __restrict__ b1) {
    int warp = (blockIdx.x * 256 + threadIdx.x) >> 5;
    int lane = threadIdx.x & 31;
    if (warp >= NN) return;
    int n = warp;
    int deg = g_deg[n];
    int off = g_off[n];
    int h8 = lane & 7;            // head index in logit phase (lane = edge*8 + h8)
    int h4 = lane >> 2;           // head owning this lane's 2 dims
    float adf = g_ad1[n * 8 + h8];

    float2 acc = make_float2(0.0f, 0.0f);
    float den = 0.0f;

    for (int base = 0; base < deg; base += 32) {
        int idx = base + lane;
        int sreg = (idx < deg) ? g_csr[off + idx] : 0;
        int cnt = min(32, deg - base);
        for (int g = 0; g < cnt; g += 4) {
            // logits for edges base+g .. base+g+3 across all 32 lanes
            int le = g + (lane >> 3);
            int sl = __shfl_sync(0xFFFFFFFFu, sreg, le);
            float e = __half2float(g_as1h[sl * 8 + h8]) + adf;
            e = (e >= 0.0f) ? e : NEG_SLOPE * e;
            float p = __expf(e);
            if (base + le >= deg) p = 0.0f;
#pragma unroll
            for (int j = 0; j < 4; j++) {
                int s = __shfl_sync(0xFFFFFFFFu, sreg, g + j);
                float pj = __shfl_sync(0xFFFFFFFFu, p, j * 8 + h4);
                float2 v = __half22float2(g_h1h[(size_t)s * 32 + lane]);
                acc.x += pj * v.x;
                acc.y += pj * v.y;
                den += pj;
            }
        }
    }

    float inv = (den > 0.0f) ? (1.0f / den) : 0.0f;
    float r0 = acc.x * inv + b1[2 * lane];
    float r1 = acc.y * inv + b1[2 * lane + 1];
    r0 = (r0 > 0.0f) ? r0 : (__expf(r0) - 1.0f);
    r1 = (r1 > 0.0f) ? r1 : (__expf(r1) - 1.0f);
    *(float2*)(g_out1 + (size_t)n * 64 + 2 * lane) = make_float2(r0, r1);
}

// ---------------- K5: g2 = elu_h @ W2 (+ layer2 attention logits), FFMA2 ----------------
__global__ void __launch_bounds__(256) k5_gemm2(
    const float* __restrict__ W2, const float* __restrict__ a2s,
    const float* __restrict__ a2d)
{
    __shared__ float sW[64 * 16];
    __shared__ float sA[32];
    for (int i = threadIdx.x; i < 64 * 16; i += blockDim.x) sW[i] = W2[i];
    for (int i = threadIdx.x; i < 32; i += blockDim.x)
        sA[i] = (i < 16) ? a2s[i] : a2d[i - 16];
    __syncthreads();

    int row = blockIdx.x * blockDim.x + threadIdx.x;
    if (row >= NN) return;

    unsigned long long acc2[8];
#pragma unroll
    for (int j = 0; j < 8; j++) acc2[j] = 0ULL;

    const float4* x4 = (const float4*)(g_out1 + (size_t)row * 64);
#pragma unroll 1
    for (int kc = 0; kc < 16; kc++) {
        float4 xv = x4[kc];
#pragma unroll
        for (int t = 0; t < 4; t++) {
            float xs = (t == 0) ? xv.x : (t == 1) ? xv.y : (t == 2) ? xv.z : xv.w;
            unsigned long long xs2 = pack2(xs, xs);
            const float4* wrow = (const float4*)(sW + (kc * 4 + t) * 16);
#pragma unroll
            for (int j4 = 0; j4 < 4; j4++) {
                F4U w;
                w.f = wrow[j4];
                ffma2(acc2[j4 * 2 + 0], xs2, w.u[0]);
                ffma2(acc2[j4 * 2 + 1], xs2, w.u[1]);
            }
        }
    }

    float acc[16];
#pragma unroll
    for (int j = 0; j < 8; j++) {
        U2F u;
        u.u = acc2[j];
        acc[j * 2] = u.f[0];
        acc[j * 2 + 1] = u.f[1];
    }

    __half* go = g_g2h + (size_t)row * 16;
#pragma unroll
    for (int j = 0; j < 16; j++) go[j] = __float2half(acc[j]);

    float s = 0.0f, d = 0.0f;
#pragma unroll
    for (int j = 0; j < 16; j++) { s += acc[j] * sA[j]; d += acc[j] * sA[16 + j]; }
    g_as2[row] = s;
    g_ad2[row] = d;
}

// ---------------- G2: warp-per-dst gather, 32-edge batched logits ----------------
__global__ void __launch_bounds__(256) g2_gather(const float* __restrict__ b2,
                                                 float* __restrict__ out) {
    int warp = (blockIdx.x * 256 + threadIdx.x) >> 5;
    int lane = threadIdx.x & 31;
    if (warp >= NN) return;
    int n = warp;
    int deg = g_deg[n];
    int off = g_off[n];
    int half = lane >> 4;      // which of 2 edges per accumulation step
    int d16 = lane & 15;       // output class
    float ad = g_ad2[n];

    float acc = 0.0f, den = 0.0f;

    for (int base = 0; base < deg; base += 32) {
        int idx = base + lane;
        int sreg = (idx < deg) ? g_csr[off + idx] : 0;
        float e = g_as2[sreg] + ad;
        e = (e >= 0.0f) ? e : NEG_SLOPE * e;
        float p = __expf(e);
        if (idx >= deg) p = 0.0f;
        int cnt = min(32, deg - base);
        for (int g = 0; g < cnt; g += 2) {
            int s = __shfl_sync(0xFFFFFFFFu, sreg, g + half);
            float pj = __shfl_sync(0xFFFFFFFFu, p, g + half);
            float v = __half2float(g_g2h[(size_t)s * 16 + d16]);
            acc += pj * v;
            den += pj;
        }
    }

    // combine the two halves
    acc += __shfl_xor_sync(0xFFFFFFFFu, acc, 16);
    den += __shfl_xor_sync(0xFFFFFFFFu, den, 16);

    float z = ((den > 0.0f) ? (acc / den) : 0.0f) + b2[d16];

    // log-softmax over 16 classes (within each 16-lane group)
    float m = z;
#pragma unroll
    for (int ofs = 1; ofs < 16; ofs <<= 1)
        m = fmaxf(m, __shfl_xor_sync(0xFFFFFFFFu, m, ofs));
    float sum = __expf(z - m);
#pragma unroll
    for (int ofs = 1; ofs < 16; ofs <<= 1)
        sum += __shfl_xor_sync(0xFFFFFFFFu, sum, ofs);
    float lse = m + logf(sum);

    if (lane < 16) out[(size_t)n * 16 + d16] = z - lse;
}

// ---------------- launcher ----------------
extern "C" void kernel_launch(void* const* d_in, const int* in_sizes, int n_in,
                              void* d_out, int out_size) {
    const float* x   = (const float*)d_in[0];
    const int*   ei  = (const int*)d_in[1];
    const float* W1  = (const float*)d_in[2];
    const float* a1s = (const float*)d_in[3];
    const float* a1d = (const float*)d_in[4];
    const float* b1  = (const float*)d_in[5];
    const float* W2  = (const float*)d_in[6];
    const float* a2s = (const float*)d_in[7];
    const float* a2d = (const float*)d_in[8];
    const float* b2  = (const float*)d_in[9];
    float* out = (float*)d_out;

    const int* src = ei;
    const int* dst = ei + EE;

    const int TB = 256;
    // CSR build
    k0_init<<<(NN + TB - 1) / TB, TB>>>();
    k_hist<<<(EE + TB - 1) / TB, TB>>>(dst);
    s1_scan<<<NBLK, SCAN_B>>>();
    s3_apply<<<NBLK, SCAN_B>>>();
    k_scatter<<<(EE + TB - 1) / TB, TB>>>(src, dst);
    // layer 1
    k1_gemm1<<<(NN + TB - 1) / TB, TB>>>(x, W1, a1s, a1d);
    g1_gather<<<(NN * 32 + TB - 1) / TB, TB>>>(b1);
    // layer 2
    k5_gemm2<<<(NN + TB - 1) / TB, TB>>>(W2, a2s, a2d);
    g2_gather<<<(NN * 32 + TB - 1) / TB, TB>>>(b2, out);
}